// round 1
// baseline (speedup 1.0000x reference)
#include <cuda_runtime.h>
#include <math.h>

#define BATCH 8
#define CIN   512
#define COUT  256
#define SDIM  512
#define HW    64

// scratch (allocation-free rule: __device__ globals)
__device__ float g_s[BATCH * CIN];                 // style modulation  [b][ci]
__device__ float g_wsq[COUT * CIN];                // sum_k w^2         [co][ci]
__device__ float g_demod[BATCH * COUT];            // scale*demod       [b][co]
__device__ float g_wp[4 * 9 * CIN * COUT];         // phase weights [phase][tap][ci][co]

// ---------------------------------------------------------------------------
// s[b,ci] = style[b,:] . (mod_weight[ci,:] * mod_scale) + mod_bias[ci]
// one warp per (b,ci)
// ---------------------------------------------------------------------------
__global__ void k_style(const float* __restrict__ style,
                        const float* __restrict__ mw,
                        const float* __restrict__ mb) {
    int idx  = blockIdx.x * 8 + (threadIdx.x >> 5);   // 4096 warps
    int lane = threadIdx.x & 31;
    int b  = idx / CIN;
    int ci = idx - b * CIN;
    const float* st = style + b * SDIM;
    const float* w  = mw + ci * SDIM;
    float acc = 0.f;
    for (int d = lane; d < SDIM; d += 32) acc += st[d] * w[d];
#pragma unroll
    for (int o = 16; o; o >>= 1) acc += __shfl_xor_sync(0xffffffffu, acc, o);
    const float mod_scale = 0.044194173824159216f;    // 1/sqrt(512)
    if (lane == 0) g_s[idx] = acc * mod_scale + mb[ci];
}

// ---------------------------------------------------------------------------
// Per (co,ci): wsq and the 4 phase 3x3 kernels from the combined 6x6 kernel
// C[a,b] = sum_{p,q} w[p,q] g[a-2+p] g[b-2+q],   g = [1,3,3,1]/4
// phase (r,c), tap (dy,dx):  P = C[2*dy+3-r, 2*dx+3-c],  dy,dx in {-1,0,1}
// ---------------------------------------------------------------------------
__global__ void k_wprep(const float* __restrict__ weight) {
    int t = blockIdx.x * blockDim.x + threadIdx.x;    // 131072 threads
    int co = t & (COUT - 1);
    int ci = t >> 8;                                  // t / 256
    const float* wp = weight + (co * CIN + ci) * 9;
    float w[3][3];
    float wsq = 0.f;
#pragma unroll
    for (int p = 0; p < 3; ++p)
#pragma unroll
        for (int q = 0; q < 3; ++q) {
            float v = wp[p * 3 + q];
            w[p][q] = v;
            wsq += v * v;
        }
    g_wsq[co * CIN + ci] = wsq;

    const float gv[4] = {0.25f, 0.75f, 0.75f, 0.25f};
    float C[6][6];
#pragma unroll
    for (int a = 0; a < 6; ++a)
#pragma unroll
        for (int bb = 0; bb < 6; ++bb) {
            float acc = 0.f;
#pragma unroll
            for (int p = 0; p < 3; ++p) {
                int ia = a - 2 + p;
                if (ia < 0 || ia > 3) continue;
#pragma unroll
                for (int q = 0; q < 3; ++q) {
                    int ib = bb - 2 + q;
                    if (ib < 0 || ib > 3) continue;
                    acc += w[p][q] * gv[ia] * gv[ib];
                }
            }
            C[a][bb] = acc;
        }

#pragma unroll
    for (int r = 0; r < 2; ++r)
#pragma unroll
        for (int c = 0; c < 2; ++c) {
            int phase = r * 2 + c;
#pragma unroll
            for (int dyi = 0; dyi < 3; ++dyi)
#pragma unroll
                for (int dxi = 0; dxi < 3; ++dxi) {
                    int tap = dyi * 3 + dxi;
                    int a = 2 * dyi + 1 - r;          // 2*(dyi-1)+3-r
                    int bcol = 2 * dxi + 1 - c;
                    g_wp[((phase * 9 + tap) * CIN + ci) * COUT + co] = C[a][bcol];
                }
        }
}

// ---------------------------------------------------------------------------
// demod[b,co] = scale * rsqrt(scale^2 * sum_ci s[b,ci]^2 * wsq[co,ci] + 1e-8)
// one warp per (b,co)
// ---------------------------------------------------------------------------
__global__ void k_demod() {
    int idx  = blockIdx.x * 8 + (threadIdx.x >> 5);   // 2048 warps
    int lane = threadIdx.x & 31;
    int b  = idx / COUT;
    int co = idx - b * COUT;
    float acc = 0.f;
    for (int ci = lane; ci < CIN; ci += 32) {
        float sv = g_s[b * CIN + ci];
        acc += sv * sv * g_wsq[co * CIN + ci];
    }
#pragma unroll
    for (int o = 16; o; o >>= 1) acc += __shfl_xor_sync(0xffffffffu, acc, o);
    const float scale  = 0.014731391274719738f;       // 1/sqrt(512*9)
    const float scale2 = 2.1701388888888888e-4f;      // 1/4608
    if (lane == 0) g_demod[idx] = scale * rsqrtf(scale2 * acc + 1e-8f);
}

// ---------------------------------------------------------------------------
// Main fused conv: one phase per blockIdx.z; 128 co x (8x8 phase-grid px) tile.
// out[b,co,2Y+r,2X+c] = m(b,co) * sum_{ci,tap} xs(b,ci,Y+dy,X+dx) * Wp
// ---------------------------------------------------------------------------
__global__ void __launch_bounds__(256) k_conv(const float* __restrict__ x,
                                              float* __restrict__ out) {
    const int phase = blockIdx.z;
    const int r = phase >> 1, c = phase & 1;
    const int b    = blockIdx.x >> 6;
    const int tile = blockIdx.x & 63;
    const int Y0 = (tile >> 3) * 8;
    const int X0 = (tile & 7) * 8;
    const int co0 = blockIdx.y * 128;

    const int tid = threadIdx.x;
    const int cog = tid >> 4;            // 0..15  -> 8 co each
    const int pxg = tid & 15;            // 0..15  -> 4 px each (row Yl, quad Xq)
    const int Yl = pxg >> 1;
    const int Xq = (pxg & 1) * 4;

    __shared__ float xs[16][10][12];     // [ci][y][x], x rows Y0-1..Y0+8, cols X0-1..X0+8
    __shared__ float ws[16][128];        // [ci][co]

    float acc[8][4];
#pragma unroll
    for (int i = 0; i < 8; ++i)
#pragma unroll
        for (int j = 0; j < 4; ++j) acc[i][j] = 0.f;

    for (int ch = 0; ch < CIN; ch += 16) {
        __syncthreads();
        // load x tile (modulated by s)
        for (int idx = tid; idx < 1600; idx += 256) {
            int k   = idx / 100;
            int rem = idx - k * 100;
            int yy  = rem / 10;
            int xx  = rem - yy * 10;
            int gy = Y0 - 1 + yy;
            int gx = X0 - 1 + xx;
            float v = 0.f;
            if ((unsigned)gy < 64u && (unsigned)gx < 64u)
                v = x[((b * CIN + ch + k) * HW + gy) * HW + gx] * g_s[b * CIN + ch + k];
            xs[k][yy][xx] = v;
        }

        for (int tap = 0; tap < 9; ++tap) {
            __syncthreads();
            const float* wg = g_wp + ((phase * 9 + tap) * CIN + ch) * COUT + co0;
            for (int idx = tid; idx < 2048; idx += 256) {
                int k  = idx >> 7;
                int co = idx & 127;
                ws[k][co] = wg[k * COUT + co];
            }
            __syncthreads();

            const int dyi = tap / 3;
            const int dxi = tap - dyi * 3;
            const int yrow = Yl + dyi;
            const int xcol = Xq + dxi;
#pragma unroll
            for (int k = 0; k < 16; ++k) {
                float xv[4];
#pragma unroll
                for (int j = 0; j < 4; ++j) xv[j] = xs[k][yrow][xcol + j];
#pragma unroll
                for (int i = 0; i < 8; ++i) {
                    float wv = ws[k][cog * 8 + i];
#pragma unroll
                    for (int j = 0; j < 4; ++j)
                        acc[i][j] = fmaf(wv, xv[j], acc[i][j]);
                }
            }
        }
    }

    // epilogue: multiply by scale*demod, write strided phase outputs
    const int Yg = Y0 + Yl;
    const int oy = 2 * Yg + r;
#pragma unroll
    for (int i = 0; i < 8; ++i) {
        int co = co0 + cog * 8 + i;
        float m = g_demod[b * COUT + co];
        float* op = out + ((size_t)(b * COUT + co) * 128 + oy) * 128;
#pragma unroll
        for (int j = 0; j < 4; ++j) {
            int ox = 2 * (X0 + Xq + j) + c;
            op[ox] = acc[i][j] * m;
        }
    }
}

// ---------------------------------------------------------------------------
extern "C" void kernel_launch(void* const* d_in, const int* in_sizes, int n_in,
                              void* d_out, int out_size) {
    const float* x          = (const float*)d_in[0];   // [8,512,64,64]
    const float* style      = (const float*)d_in[1];   // [8,512]
    const float* weight     = (const float*)d_in[2];   // [1,256,512,3,3]
    const float* mod_weight = (const float*)d_in[3];   // [512,512]
    const float* mod_bias   = (const float*)d_in[4];   // [512]
    float* out = (float*)d_out;                        // [8,256,128,128]

    k_style<<<512, 256>>>(style, mod_weight, mod_bias);
    k_wprep<<<512, 256>>>(weight);
    k_demod<<<256, 256>>>();
    dim3 grid(512, 2, 4);
    k_conv<<<grid, 256>>>(x, out);
}